// round 2
// baseline (speedup 1.0000x reference)
#include <cuda_runtime.h>

#define B_ 16384
#define S_ 32
#define E_ 128
#define H_ 4
#define DH_ 32
#define O_ 128
#define SCALE_ 0.17677669529663687f  // 1/sqrt(32)

typedef unsigned long long u64;

__device__ __forceinline__ u64 pk2(float lo, float hi) {
    u64 r; asm("mov.b64 %0, {%1,%2};" : "=l"(r) : "f"(lo), "f"(hi)); return r;
}
__device__ __forceinline__ float2 up2(u64 v) {
    float2 f; asm("mov.b64 {%0,%1}, %2;" : "=f"(f.x), "=f"(f.y) : "l"(v)); return f;
}
// packed fp32x2 FMA: d = a*b + d   (sm_100+ PTX; ptxas never emits FFMA2 from C++)
__device__ __forceinline__ void fma2(u64& d, u64 a, u64 b) {
    asm("fma.rn.f32x2 %0, %1, %2, %3;" : "=l"(d) : "l"(a), "l"(b), "l"(d));
}

// Shared layout (floats):
//  xp  [16][256]  : x pairs; xp[sp][2e+p] = x[2sp+p][e]           (4096)
//  qs  [4][32][32]: Q*scale, [h][s][d]                            (4096)
//  ks  [4][32][32]: K, [h][t][d]                                  (4096)
//  vs  [4][32][32]: V, [h][t][d]                                  (4096)
//  as_ [4][32][32]: scores -> softmax A, [h][s][t]                (4096)
//  hdT [128][32]  : Hd transposed, [h*32+d][s]                    (4096)
#define SMEM_FLOATS 24576

extern __shared__ float smem[];

__global__ __launch_bounds__(256, 2)
void attn_fused_kernel(const float* __restrict__ x,
                       const float* __restrict__ wq,
                       const float* __restrict__ wk,
                       const float* __restrict__ wv,
                       const float* __restrict__ wo,
                       float* __restrict__ out) {
    float* xp  = smem;
    float* qs  = smem + 4096;
    float* ks  = smem + 8192;
    float* vs  = smem + 12288;
    float* as_ = smem + 16384;
    float* hdT = smem + 20480;

    const int tid = threadIdx.x;
    const long long b = blockIdx.x;
    const float* xb = x + b * (long long)(S_ * E_);

    // ---- load x into paired-transposed smem ----
#pragma unroll
    for (int i = 0; i < 16; i++) {
        int idx = tid + i * 256;          // idx = s*128 + e
        int s = idx >> 7, e = idx & 127;
        xp[(s >> 1) * 256 + e * 2 + (s & 1)] = xb[idx];
    }
    __syncthreads();

    // ---- phase 1: QKV projections (192 threads x 2 columns, FFMA2) ----
    if (tid < 192) {
        u64 acc0[16], acc1[16];
#pragma unroll
        for (int i = 0; i < 16; i++) { acc0[i] = 0ULL; acc1[i] = 0ULL; }

        const int c0 = tid, c1 = tid + 192;
        const int m0 = c0 >> 7, h0 = (c0 >> 5) & 3, d0 = c0 & 31;
        const int m1 = c1 >> 7, h1 = (c1 >> 5) & 3, d1 = c1 & 31;
        const float* w0 = ((m0 == 0) ? wq : ((m0 == 1) ? wk : wv)) + h0 * (E_ * DH_) + d0;
        const float* w1 = ((m1 == 1) ? wk : wv) + h1 * (E_ * DH_) + d1;

        const float4* xp4 = (const float4*)xp;  // [16][64]
#pragma unroll 2
        for (int e2 = 0; e2 < 64; e2++) {
            float w0a = __ldg(w0 + (e2 * 2) * DH_);
            float w0b = __ldg(w0 + (e2 * 2 + 1) * DH_);
            float w1a = __ldg(w1 + (e2 * 2) * DH_);
            float w1b = __ldg(w1 + (e2 * 2 + 1) * DH_);
            u64 W0a = pk2(w0a, w0a), W0b = pk2(w0b, w0b);
            u64 W1a = pk2(w1a, w1a), W1b = pk2(w1b, w1b);
#pragma unroll
            for (int sp = 0; sp < 16; sp++) {
                float4 xv = xp4[sp * 64 + e2];
                u64 xa = pk2(xv.x, xv.y);
                u64 xc = pk2(xv.z, xv.w);
                fma2(acc0[sp], xa, W0a);
                fma2(acc0[sp], xc, W0b);
                fma2(acc1[sp], xa, W1a);
                fma2(acc1[sp], xc, W1b);
            }
        }
        const float sc0 = (m0 == 0) ? SCALE_ : 1.0f;
        float* dst0 = ((m0 == 0) ? qs : ((m0 == 1) ? ks : vs)) + h0 * 1024 + d0;
        float* dst1 = ((m1 == 1) ? ks : vs) + h1 * 1024 + d1;
#pragma unroll
        for (int sp = 0; sp < 16; sp++) {
            float2 v0 = up2(acc0[sp]);
            float2 v1 = up2(acc1[sp]);
            dst0[(2 * sp) * 32]     = v0.x * sc0;
            dst0[(2 * sp + 1) * 32] = v0.y * sc0;
            dst1[(2 * sp) * 32]     = v1.x;
            dst1[(2 * sp + 1) * 32] = v1.y;
        }
    }
    __syncthreads();

    // ---- phase 2: scores[h][s][t] = Q[h,s,:] . K[h,t,:] ----
    {
        const int h = tid >> 6, s = (tid >> 1) & 31, th = tid & 1;
        const float4* q4 = (const float4*)(qs + h * 1024 + s * 32);
        float4 qr[8];
#pragma unroll
        for (int j = 0; j < 8; j++) qr[j] = q4[j];
#pragma unroll
        for (int t = 0; t < 16; t++) {
            const int tt = th * 16 + t;
            const float4* k4 = (const float4*)(ks + h * 1024 + tt * 32);
            float acc = 0.0f;
#pragma unroll
            for (int j = 0; j < 8; j++) {
                float4 kv = k4[j];
                acc += qr[j].x * kv.x + qr[j].y * kv.y + qr[j].z * kv.z + qr[j].w * kv.w;
            }
            as_[h * 1024 + s * 32 + tt] = acc;
        }
    }
    __syncthreads();

    // ---- phase 3: softmax over t (one thread per (h,s) row) ----
    if (tid < 128) {
        float* row = as_ + tid * 32;   // [h][s][*] with h = tid>>5, s = tid&31
        float v[32];
        float mx = -1e30f;
#pragma unroll
        for (int t = 0; t < 32; t++) { v[t] = row[t]; mx = fmaxf(mx, v[t]); }
        float sum = 0.0f;
#pragma unroll
        for (int t = 0; t < 32; t++) { v[t] = expf(v[t] - mx); sum += v[t]; }
        const float inv = 1.0f / sum;
#pragma unroll
        for (int t = 0; t < 32; t++) row[t] = v[t] * inv;
    }
    __syncthreads();

    // ---- phase 4: Hd[h][s][d] = sum_t A[h,s,t] * V[h,t,d]; store transposed ----
    {
        const int h = tid >> 6, s = (tid >> 1) & 31, dh = tid & 1;
        const float* arow = as_ + h * 1024 + s * 32;
        float ar[32];
#pragma unroll
        for (int t = 0; t < 32; t++) ar[t] = arow[t];
        float acc[16];
#pragma unroll
        for (int i = 0; i < 16; i++) acc[i] = 0.0f;
#pragma unroll
        for (int t = 0; t < 32; t++) {
            const float av = ar[t];
            const float4* vrow = (const float4*)(vs + h * 1024 + t * 32 + dh * 16);
            float4 v0 = vrow[0], v1 = vrow[1], v2 = vrow[2], v3 = vrow[3];
            acc[0]  += av * v0.x; acc[1]  += av * v0.y; acc[2]  += av * v0.z; acc[3]  += av * v0.w;
            acc[4]  += av * v1.x; acc[5]  += av * v1.y; acc[6]  += av * v1.z; acc[7]  += av * v1.w;
            acc[8]  += av * v2.x; acc[9]  += av * v2.y; acc[10] += av * v2.z; acc[11] += av * v2.w;
            acc[12] += av * v3.x; acc[13] += av * v3.y; acc[14] += av * v3.z; acc[15] += av * v3.w;
        }
        float* hbase = hdT + (h * 32 + dh * 16) * 32 + s;
#pragma unroll
        for (int i = 0; i < 16; i++) hbase[i * 32] = acc[i];
    }
    __syncthreads();

    // ---- phase 5: out[s][o] = sum_{h,d} Hd[h,s,d] * wo[h][d][o]  (FFMA2 over s-pairs) ----
    {
        const int o = tid & 127, sh = tid >> 7;  // s base = sh*16
        u64 acc2[8];
#pragma unroll
        for (int i = 0; i < 8; i++) acc2[i] = 0ULL;
#pragma unroll 4
        for (int hd = 0; hd < 128; hd++) {
            const float wv = __ldg(wo + hd * O_ + o);
            const u64 W = pk2(wv, wv);
            const float4* hr = (const float4*)(hdT + hd * 32 + sh * 16);
#pragma unroll
            for (int j = 0; j < 4; j++) {
                float4 f = hr[j];
                fma2(acc2[2 * j],     pk2(f.x, f.y), W);
                fma2(acc2[2 * j + 1], pk2(f.z, f.w), W);
            }
        }
        float* ob = out + b * (long long)(S_ * O_) + o;
#pragma unroll
        for (int j = 0; j < 8; j++) {
            float2 f = up2(acc2[j]);
            const int s = sh * 16 + 2 * j;
            ob[s * O_] = f.x;
            ob[(s + 1) * O_] = f.y;
        }
    }
}

extern "C" void kernel_launch(void* const* d_in, const int* in_sizes, int n_in,
                              void* d_out, int out_size) {
    const float* x  = (const float*)d_in[0];
    const float* wq = (const float*)d_in[1];
    const float* wk = (const float*)d_in[2];
    const float* wv = (const float*)d_in[3];
    const float* wo = (const float*)d_in[4];
    float* out = (float*)d_out;

    // idempotent, deterministic; executes immediately (not a captured stream op)
    cudaFuncSetAttribute(attn_fused_kernel,
                         cudaFuncAttributeMaxDynamicSharedMemorySize,
                         SMEM_FLOATS * (int)sizeof(float));

    attn_fused_kernel<<<B_, 256, SMEM_FLOATS * sizeof(float)>>>(x, wq, wk, wv, wo, out);
}

// round 3
// speedup vs baseline: 3.3751x; 3.3751x over previous
#include <cuda_runtime.h>
#include <cuda_fp16.h>

#define B_ 16384
#define SCALE_ 0.17677669529663687f  // 1/sqrt(32)

typedef unsigned u32;

// ---- precomputed weight fragment buffers (hi/lo fp16 split, mma B-fragment order) ----
// qkv: 48 n-tiles x 8 k-tiles x 32 lanes x {b0,b1}
__device__ __align__(16) u32 g_wqkv_h[48 * 8 * 32 * 2];
__device__ __align__(16) u32 g_wqkv_l[48 * 8 * 32 * 2];
// wo: 16 n-tiles x 8 k-tiles x 32 lanes x {b0,b1}
__device__ __align__(16) u32 g_wo_h[16 * 8 * 32 * 2];
__device__ __align__(16) u32 g_wo_l[16 * 8 * 32 * 2];

__device__ __forceinline__ void split_pair(float a, float b, u32& hi, u32& lo) {
    __half ha = __float2half_rn(a), hb = __float2half_rn(b);
    __half2 h2 = __halves2half2(ha, hb);
    hi = *(u32*)&h2;
    __half2 l2 = __floats2half2_rn(a - __half2float(ha), b - __half2float(hb));
    lo = *(u32*)&l2;
}
__device__ __forceinline__ void split_one(float v, __half* ph, __half* pl) {
    __half h = __float2half_rn(v);
    *ph = h;
    *pl = __float2half_rn(v - __half2float(h));
}

__device__ __forceinline__ void mma16816(float* d, const u32* a, const u32* b) {
    asm volatile(
        "mma.sync.aligned.m16n8k16.row.col.f32.f16.f16.f32 "
        "{%0,%1,%2,%3}, {%4,%5,%6,%7}, {%8,%9}, {%0,%1,%2,%3};\n"
        : "+f"(d[0]), "+f"(d[1]), "+f"(d[2]), "+f"(d[3])
        : "r"(a[0]), "r"(a[1]), "r"(a[2]), "r"(a[3]), "r"(b[0]), "r"(b[1]));
}

// A-fragment (m16k16, row-major halfs, row stride `stride` halfs).
// base must already point at element [row0+g][col0+2*tig].
__device__ __forceinline__ void loadA(u32* fr, const __half* base, int stride) {
    fr[0] = *(const u32*)(base);
    fr[1] = *(const u32*)(base + 8 * stride);
    fr[2] = *(const u32*)(base + 8);
    fr[3] = *(const u32*)(base + 8 * stride + 8);
}

// ---- prep kernel: split weights to fp16 hi/lo in fragment order ----
__global__ void prep_weights(const float* __restrict__ wq, const float* __restrict__ wk,
                             const float* __restrict__ wv, const float* __restrict__ wo) {
    int i = blockIdx.x * blockDim.x + threadIdx.x;
    if (i < 48 * 8 * 32 * 2) {
        int r = i & 1;
        int ln = (i >> 1) & 31;
        int kt = (i >> 6) & 7;
        int j = i >> 9;  // 0..47
        int tig = ln & 3, g = ln >> 2;
        int m = j >> 4, h = (j >> 2) & 3, dt = j & 3;
        const float* w = ((m == 0) ? wq : ((m == 1) ? wk : wv)) + h * 4096;
        int e0 = kt * 16 + r * 8 + 2 * tig;
        int d = dt * 8 + g;
        float w0 = w[e0 * 32 + d];
        float w1 = w[(e0 + 1) * 32 + d];
        u32 hi, lo;
        split_pair(w0, w1, hi, lo);
        g_wqkv_h[i] = hi;
        g_wqkv_l[i] = lo;
    } else if (i < 48 * 8 * 32 * 2 + 16 * 8 * 32 * 2) {
        int k = i - 48 * 8 * 32 * 2;
        int r = k & 1;
        int ln = (k >> 1) & 31;
        int kt = (k >> 6) & 7;
        int nt = k >> 9;  // 0..15
        int tig = ln & 3, g = ln >> 2;
        int hd0 = kt * 16 + r * 8 + 2 * tig;
        int o = nt * 8 + g;
        float w0 = wo[hd0 * 128 + o];
        float w1 = wo[(hd0 + 1) * 128 + o];
        u32 hi, lo;
        split_pair(w0, w1, hi, lo);
        g_wo_h[k] = hi;
        g_wo_l[k] = lo;
    }
}

// ---- smem byte offsets ----
// XH/XL [32][136] halfs (8704 B each) -> reused as HDH/HDL after phase 2
// QH/QL/KH/KL/VTH/VTL [4][32][40] halfs (10240 B each); KH/KL reused as AH/AL
// SC [4][32][33] floats (16896 B)
#define OFF_XH 0
#define OFF_XL 8704
#define OFF_QH 17408
#define OFF_QL 27648
#define OFF_KH 37888
#define OFF_KL 48128
#define OFF_VTH 58368
#define OFF_VTL 68608
#define OFF_SC 78848
#define SMEM_BYTES 95744

extern __shared__ char smem_raw[];

__global__ __launch_bounds__(256, 2)
void attn_mma_kernel(const float* __restrict__ x, float* __restrict__ out) {
    __half* XH = (__half*)(smem_raw + OFF_XH);
    __half* XL = (__half*)(smem_raw + OFF_XL);
    __half* QH = (__half*)(smem_raw + OFF_QH);
    __half* QL = (__half*)(smem_raw + OFF_QL);
    __half* KH = (__half*)(smem_raw + OFF_KH);
    __half* KL = (__half*)(smem_raw + OFF_KL);
    __half* VTH = (__half*)(smem_raw + OFF_VTH);
    __half* VTL = (__half*)(smem_raw + OFF_VTL);
    float* SC = (float*)(smem_raw + OFF_SC);
    __half* AH = KH;   // reuse (K dead after phase 2)
    __half* AL = KL;
    __half* HDH = XH;  // reuse (x dead after phase 1)
    __half* HDL = XL;

    const int tid = threadIdx.x;
    const int lane = tid & 31, w = tid >> 5;
    const int g = lane >> 2, tig = lane & 3;
    const long long b = blockIdx.x;

    // ---- load x, split fp16 hi/lo ----
    const float2* xb2 = (const float2*)(x + b * 4096LL);
#pragma unroll
    for (int i = 0; i < 8; i++) {
        int idx = tid + i * 256;  // over 2048 float2: s = idx/64, e2 = idx%64
        int s = idx >> 6, e2 = idx & 63;
        float2 v = xb2[idx];
        u32 hi, lo;
        split_pair(v.x, v.y, hi, lo);
        *(u32*)&XH[s * 136 + e2 * 2] = hi;
        *(u32*)&XL[s * 136 + e2 * 2] = lo;
    }
    __syncthreads();

    // ---- phase 1: QKV = X[32,128] @ Wqkv[128,384], 3-MMA fp16 split ----
    {
        float acc[2][6][4];
#pragma unroll
        for (int mt = 0; mt < 2; mt++)
#pragma unroll
            for (int nj = 0; nj < 6; nj++)
#pragma unroll
                for (int c = 0; c < 4; c++) acc[mt][nj][c] = 0.0f;

#pragma unroll
        for (int kt = 0; kt < 8; kt++) {
            u32 ah[2][4], al[2][4];
#pragma unroll
            for (int mt = 0; mt < 2; mt++) {
                const __half* pb = XH + (mt * 16 + g) * 136 + kt * 16 + 2 * tig;
                loadA(ah[mt], pb, 136);
                loadA(al[mt], pb + (OFF_XL - OFF_XH) / 2, 136);
            }
#pragma unroll
            for (int nj = 0; nj < 6; nj++) {
                int j = w * 6 + nj;
                uint2 bh = __ldg((const uint2*)g_wqkv_h + (j * 8 + kt) * 32 + lane);
                uint2 bl = __ldg((const uint2*)g_wqkv_l + (j * 8 + kt) * 32 + lane);
#pragma unroll
                for (int mt = 0; mt < 2; mt++) {
                    mma16816(acc[mt][nj], ah[mt], (const u32*)&bh);
                    mma16816(acc[mt][nj], ah[mt], (const u32*)&bl);
                    mma16816(acc[mt][nj], al[mt], (const u32*)&bh);
                }
            }
        }
        // epilogue: split + scatter to Q/K/V smem
#pragma unroll
        for (int nj = 0; nj < 6; nj++) {
            int j = w * 6 + nj;
            int m = j >> 4, h = (j >> 2) & 3, dt = j & 3;
#pragma unroll
            for (int mt = 0; mt < 2; mt++) {
                float c0 = acc[mt][nj][0], c1 = acc[mt][nj][1];
                float c2 = acc[mt][nj][2], c3 = acc[mt][nj][3];
                int r0 = mt * 16 + g, r1 = r0 + 8;
                int d0 = dt * 8 + 2 * tig;
                if (m == 0) {
                    c0 *= SCALE_; c1 *= SCALE_; c2 *= SCALE_; c3 *= SCALE_;
                    u32 hi, lo;
                    split_pair(c0, c1, hi, lo);
                    *(u32*)&QH[h * 1280 + r0 * 40 + d0] = hi;
                    *(u32*)&QL[h * 1280 + r0 * 40 + d0] = lo;
                    split_pair(c2, c3, hi, lo);
                    *(u32*)&QH[h * 1280 + r1 * 40 + d0] = hi;
                    *(u32*)&QL[h * 1280 + r1 * 40 + d0] = lo;
                } else if (m == 1) {
                    u32 hi, lo;
                    split_pair(c0, c1, hi, lo);
                    *(u32*)&KH[h * 1280 + r0 * 40 + d0] = hi;
                    *(u32*)&KL[h * 1280 + r0 * 40 + d0] = lo;
                    split_pair(c2, c3, hi, lo);
                    *(u32*)&KH[h * 1280 + r1 * 40 + d0] = hi;
                    *(u32*)&KL[h * 1280 + r1 * 40 + d0] = lo;
                } else {
                    // V transposed: VT[h][d][t]
                    split_one(c0, &VTH[h * 1280 + d0 * 40 + r0], &VTL[h * 1280 + d0 * 40 + r0]);
                    split_one(c1, &VTH[h * 1280 + (d0 + 1) * 40 + r0], &VTL[h * 1280 + (d0 + 1) * 40 + r0]);
                    split_one(c2, &VTH[h * 1280 + d0 * 40 + r1], &VTL[h * 1280 + d0 * 40 + r1]);
                    split_one(c3, &VTH[h * 1280 + (d0 + 1) * 40 + r1], &VTL[h * 1280 + (d0 + 1) * 40 + r1]);
                }
            }
        }
    }
    __syncthreads();

    // ---- phase 2: scores[h] = Q[h] @ K[h]^T ----
    {
        int h = w >> 1, mt = w & 1;
        float acc[4][4];
#pragma unroll
        for (int nt = 0; nt < 4; nt++)
#pragma unroll
            for (int c = 0; c < 4; c++) acc[nt][c] = 0.0f;

#pragma unroll
        for (int kt = 0; kt < 2; kt++) {
            u32 ah[4], al[4];
            const __half* pq = QH + h * 1280 + (mt * 16 + g) * 40 + kt * 16 + 2 * tig;
            loadA(ah, pq, 40);
            loadA(al, pq + (OFF_QL - OFF_QH) / 2, 40);
#pragma unroll
            for (int nt = 0; nt < 4; nt++) {
                const __half* pk = KH + h * 1280 + (nt * 8 + g) * 40 + kt * 16 + 2 * tig;
                u32 bh[2], bl[2];
                bh[0] = *(const u32*)pk;
                bh[1] = *(const u32*)(pk + 8);
                const __half* pkl = pk + (OFF_KL - OFF_KH) / 2;
                bl[0] = *(const u32*)pkl;
                bl[1] = *(const u32*)(pkl + 8);
                mma16816(acc[nt], ah, bh);
                mma16816(acc[nt], ah, bl);
                mma16816(acc[nt], al, bh);
            }
        }
#pragma unroll
        for (int nt = 0; nt < 4; nt++) {
            float* p0 = SC + h * 1056 + (mt * 16 + g) * 33 + nt * 8 + 2 * tig;
            float* p1 = SC + h * 1056 + (mt * 16 + g + 8) * 33 + nt * 8 + 2 * tig;
            p0[0] = acc[nt][0]; p0[1] = acc[nt][1];
            p1[0] = acc[nt][2]; p1[1] = acc[nt][3];
        }
    }
    __syncthreads();

    // ---- phase 3: exact fp32 softmax; write A hi/lo ----
    if (tid < 128) {
        int h = tid >> 5, s = tid & 31;
        const float* row = SC + h * 1056 + s * 33;
        float v[32], mx = -1e30f;
#pragma unroll
        for (int t = 0; t < 32; t++) { v[t] = row[t]; mx = fmaxf(mx, v[t]); }
        float sum = 0.0f;
#pragma unroll
        for (int t = 0; t < 32; t++) { v[t] = expf(v[t] - mx); sum += v[t]; }
        float inv = 1.0f / sum;
        __half* pah = AH + h * 1280 + s * 40;
        __half* pal = AL + h * 1280 + s * 40;
#pragma unroll
        for (int t = 0; t < 32; t++) split_one(v[t] * inv, &pah[t], &pal[t]);
    }
    __syncthreads();

    // ---- phase 4: Hd[h] = A[h] @ V[h]; write Hd hi/lo [s][h*32+d] ----
    {
        int h = w >> 1, mt = w & 1;
        float acc[4][4];
#pragma unroll
        for (int nt = 0; nt < 4; nt++)
#pragma unroll
            for (int c = 0; c < 4; c++) acc[nt][c] = 0.0f;

#pragma unroll
        for (int kt = 0; kt < 2; kt++) {
            u32 ah[4], al[4];
            const __half* pa = AH + h * 1280 + (mt * 16 + g) * 40 + kt * 16 + 2 * tig;
            loadA(ah, pa, 40);
            loadA(al, pa + (OFF_KL - OFF_KH) / 2, 40);
#pragma unroll
            for (int nt = 0; nt < 4; nt++) {
                const __half* pv = VTH + h * 1280 + (nt * 8 + g) * 40 + kt * 16 + 2 * tig;
                u32 bh[2], bl[2];
                bh[0] = *(const u32*)pv;
                bh[1] = *(const u32*)(pv + 8);
                const __half* pvl = pv + (OFF_VTL - OFF_VTH) / 2;
                bl[0] = *(const u32*)pvl;
                bl[1] = *(const u32*)(pvl + 8);
                mma16816(acc[nt], ah, bh);
                mma16816(acc[nt], ah, bl);
                mma16816(acc[nt], al, bh);
            }
        }
#pragma unroll
        for (int nt = 0; nt < 4; nt++) {
            int col = h * 32 + nt * 8 + 2 * tig;
            int r0 = mt * 16 + g, r1 = r0 + 8;
            u32 hi, lo;
            split_pair(acc[nt][0], acc[nt][1], hi, lo);
            *(u32*)&HDH[r0 * 136 + col] = hi;
            *(u32*)&HDL[r0 * 136 + col] = lo;
            split_pair(acc[nt][2], acc[nt][3], hi, lo);
            *(u32*)&HDH[r1 * 136 + col] = hi;
            *(u32*)&HDL[r1 * 136 + col] = lo;
        }
    }
    __syncthreads();

    // ---- phase 5: out = Hd[32,128] @ WoFlat[128,128] ----
    {
        float acc[2][2][4];
#pragma unroll
        for (int mt = 0; mt < 2; mt++)
#pragma unroll
            for (int n = 0; n < 2; n++)
#pragma unroll
                for (int c = 0; c < 4; c++) acc[mt][n][c] = 0.0f;

#pragma unroll
        for (int kt = 0; kt < 8; kt++) {
            u32 ah[2][4], al[2][4];
#pragma unroll
            for (int mt = 0; mt < 2; mt++) {
                const __half* pb = HDH + (mt * 16 + g) * 136 + kt * 16 + 2 * tig;
                loadA(ah[mt], pb, 136);
                loadA(al[mt], pb + (OFF_XL - OFF_XH) / 2, 136);
            }
#pragma unroll
            for (int ntl = 0; ntl < 2; ntl++) {
                int nt = w * 2 + ntl;
                uint2 bh = __ldg((const uint2*)g_wo_h + (nt * 8 + kt) * 32 + lane);
                uint2 bl = __ldg((const uint2*)g_wo_l + (nt * 8 + kt) * 32 + lane);
#pragma unroll
                for (int mt = 0; mt < 2; mt++) {
                    mma16816(acc[mt][ntl], ah[mt], (const u32*)&bh);
                    mma16816(acc[mt][ntl], ah[mt], (const u32*)&bl);
                    mma16816(acc[mt][ntl], al[mt], (const u32*)&bh);
                }
            }
        }
        float* ob = out + b * 4096LL;
#pragma unroll
        for (int mt = 0; mt < 2; mt++)
#pragma unroll
            for (int ntl = 0; ntl < 2; ntl++) {
                int nt = w * 2 + ntl;
                int r0 = mt * 16 + g, c = nt * 8 + 2 * tig;
                *(float2*)&ob[r0 * 128 + c] = make_float2(acc[mt][ntl][0], acc[mt][ntl][1]);
                *(float2*)&ob[(r0 + 8) * 128 + c] = make_float2(acc[mt][ntl][2], acc[mt][ntl][3]);
            }
    }
}

extern "C" void kernel_launch(void* const* d_in, const int* in_sizes, int n_in,
                              void* d_out, int out_size) {
    const float* x  = (const float*)d_in[0];
    const float* wq = (const float*)d_in[1];
    const float* wk = (const float*)d_in[2];
    const float* wv = (const float*)d_in[3];
    const float* wo = (const float*)d_in[4];
    float* out = (float*)d_out;

    cudaFuncSetAttribute(attn_mma_kernel,
                         cudaFuncAttributeMaxDynamicSharedMemorySize, SMEM_BYTES);

    prep_weights<<<128, 256>>>(wq, wk, wv, wo);
    attn_mma_kernel<<<B_, 256, SMEM_BYTES>>>(x, out);
}